// round 1
// baseline (speedup 1.0000x reference)
#include <cuda_runtime.h>
#include <cuda_bf16.h>
#include <math.h>

// Problem constants
#define BB 2
#define LL 2048
#define D_MODEL 768
#define D_INNER 1536
#define DT_RANK 16
#define D_STATE 16
#define D_CONV 4
#define MROWS (BB*LL)          // 4096
#define N_IN (2*D_INNER)       // 3072
#define N_DBL (DT_RANK + 2*D_STATE) // 48

// Scratch (static __device__ — no allocation in kernel_launch)
__device__ float g_xz[(size_t)MROWS * N_IN];       // [4096,3072]
__device__ float g_xconv[(size_t)MROWS * D_INNER]; // [4096,1536]
__device__ float g_xdbl[(size_t)MROWS * N_DBL];    // [4096,48]
__device__ float g_dt[(size_t)MROWS * D_INNER];    // [4096,1536]
__device__ float g_yg[(size_t)MROWS * D_INNER];    // [4096,1536]

// ---------------------------------------------------------------------------
// Classic 128x128x8 FP32 SGEMM, row-major A[M,K] * B[K,N] -> C[M,N]
// Requires M%128==0, N%128==0, K%8==0 (true for all shapes here).
// ---------------------------------------------------------------------------
#define BM 128
#define BN 128
#define BK 8
#define TM 8
#define TN 8

__global__ __launch_bounds__(256) void sgemm_kernel(
    const float* __restrict__ A, const float* __restrict__ B,
    float* __restrict__ C, int M, int N, int K)
{
    __shared__ float As[BK][BM];
    __shared__ float Bs[BK][BN];

    const int tid = threadIdx.x;
    const int bx = blockIdx.x, by = blockIdx.y;

    // A tile loaders: 128 rows x 8 k -> 256 float4 (2 per row along K)
    const int arow  = tid >> 1;          // 0..127
    const int acol4 = (tid & 1) * 4;     // 0 or 4
    // B tile loaders: 8 k rows x 128 n -> 256 float4
    const int brow  = tid >> 5;          // 0..7
    const int bcol4 = (tid & 31) * 4;    // 0..124

    const int tx = tid & 15;             // col group
    const int ty = tid >> 4;             // row group

    const float* Ab = A + (size_t)(by * BM) * K;
    const float* Bb = B + bx * BN;

    float acc[TM][TN];
    #pragma unroll
    for (int i = 0; i < TM; i++)
        #pragma unroll
        for (int j = 0; j < TN; j++) acc[i][j] = 0.f;

    for (int k0 = 0; k0 < K; k0 += BK) {
        float4 av = *(const float4*)(Ab + (size_t)arow * K + k0 + acol4);
        As[acol4 + 0][arow] = av.x;
        As[acol4 + 1][arow] = av.y;
        As[acol4 + 2][arow] = av.z;
        As[acol4 + 3][arow] = av.w;
        float4 bv = *(const float4*)(Bb + (size_t)(k0 + brow) * N + bcol4);
        *(float4*)(&Bs[brow][bcol4]) = bv;
        __syncthreads();

        #pragma unroll
        for (int k = 0; k < BK; k++) {
            float ra[TM], rb[TN];
            #pragma unroll
            for (int i = 0; i < TM; i++) ra[i] = As[k][ty * TM + i];
            #pragma unroll
            for (int j = 0; j < TN; j++) rb[j] = Bs[k][tx * TN + j];
            #pragma unroll
            for (int i = 0; i < TM; i++)
                #pragma unroll
                for (int j = 0; j < TN; j++)
                    acc[i][j] += ra[i] * rb[j];
        }
        __syncthreads();
    }

    float* Cb = C + (size_t)(by * BM + ty * TM) * N + bx * BN + tx * TN;
    #pragma unroll
    for (int i = 0; i < TM; i++) {
        #pragma unroll
        for (int j = 0; j < TN; j += 4) {
            float4 v = make_float4(acc[i][j], acc[i][j+1], acc[i][j+2], acc[i][j+3]);
            *(float4*)(Cb + (size_t)i * N + j) = v;
        }
    }
}

// ---------------------------------------------------------------------------
// Causal depthwise conv1d (width 4) + silu.  x_inner read in-place from g_xz.
// ---------------------------------------------------------------------------
__global__ void conv_silu_kernel(const float* __restrict__ conv_w,
                                 const float* __restrict__ conv_b)
{
    int idx = blockIdx.x * blockDim.x + threadIdx.x;   // over 4096*1536
    if (idx >= MROWS * D_INNER) return;
    int d = idx % D_INNER;
    int r = idx / D_INNER;
    int l = r % LL;

    float w0 = conv_w[d*4+0], w1 = conv_w[d*4+1], w2 = conv_w[d*4+2], w3 = conv_w[d*4+3];
    const float* base = g_xz + (size_t)r * N_IN + d;

    float acc = conv_b[d] + w3 * base[0];
    if (l >= 1) acc += w2 * base[-(size_t)N_IN];
    if (l >= 2) acc += w1 * base[-2*(size_t)N_IN];
    if (l >= 3) acc += w0 * base[-3*(size_t)N_IN];
    g_xconv[idx] = acc / (1.f + __expf(-acc));   // silu
}

// ---------------------------------------------------------------------------
// x_dbl = x_conv @ W_x  ([4096,1536] x [1536,48]).
// Block: 64 rows x 48 cols. 256 threads: (ty 0..15 row, tx 0..15 col base),
// each thread: 4 rows (stride 16) x 3 cols (c, c+16, c+32).
// ---------------------------------------------------------------------------
__global__ __launch_bounds__(256) void xdbl_kernel(const float* __restrict__ Wx)
{
    const int tx = threadIdx.x & 15;
    const int ty = threadIdx.x >> 4;
    const int r0 = blockIdx.x * 64;

    float acc[4][3] = {};
    #pragma unroll 4
    for (int k = 0; k < D_INNER; k++) {
        float w0 = Wx[k * N_DBL + tx];
        float w1 = Wx[k * N_DBL + tx + 16];
        float w2 = Wx[k * N_DBL + tx + 32];
        #pragma unroll
        for (int rr = 0; rr < 4; rr++) {
            float xv = g_xconv[(size_t)(r0 + ty + rr * 16) * D_INNER + k];
            acc[rr][0] += xv * w0;
            acc[rr][1] += xv * w1;
            acc[rr][2] += xv * w2;
        }
    }
    #pragma unroll
    for (int rr = 0; rr < 4; rr++) {
        int r = r0 + ty + rr * 16;
        g_xdbl[(size_t)r * N_DBL + tx]      = acc[rr][0];
        g_xdbl[(size_t)r * N_DBL + tx + 16] = acc[rr][1];
        g_xdbl[(size_t)r * N_DBL + tx + 32] = acc[rr][2];
    }
}

// ---------------------------------------------------------------------------
// dt = softplus(dt_low @ W_dt + b_dt)    K=16, thread per output.
// ---------------------------------------------------------------------------
__global__ void dt_kernel(const float* __restrict__ Wdt, const float* __restrict__ bdt)
{
    int idx = blockIdx.x * blockDim.x + threadIdx.x;
    if (idx >= MROWS * D_INNER) return;
    int d = idx % D_INNER;
    int r = idx / D_INNER;
    float acc = bdt[d];
    #pragma unroll
    for (int k = 0; k < DT_RANK; k++)
        acc += g_xdbl[(size_t)r * N_DBL + k] * Wdt[(size_t)k * D_INNER + d];
    g_dt[idx] = (acc > 20.f) ? acc : log1pf(__expf(acc));
}

// ---------------------------------------------------------------------------
// Selective scan.  Thread layout: 16 lanes per channel (one per state n),
// 16 channels per 256-thread block.  y reduced over n by shfl-xor within
// aligned 16-lane groups.  Epilogue fuses +u*D and silu(z) gate.
// ---------------------------------------------------------------------------
__global__ __launch_bounds__(256) void scan_kernel(
    const float* __restrict__ A_log, const float* __restrict__ Dvec)
{
    const int n  = threadIdx.x & 15;
    const int ch = blockIdx.x * 16 + (threadIdx.x >> 4);  // 0..3071
    const int b  = ch / D_INNER;
    const int d  = ch % D_INNER;

    const float A  = -__expf(A_log[d * D_STATE + n]);
    const float Dd = Dvec[d];

    const float* xc  = g_xconv + (size_t)b * LL * D_INNER + d;
    const float* dtp = g_dt    + (size_t)b * LL * D_INNER + d;
    const float* bc  = g_xdbl  + (size_t)b * LL * N_DBL;
    const float* zp  = g_xz    + (size_t)b * LL * N_IN + D_INNER + d;
    float*       yp  = g_yg    + (size_t)b * LL * D_INNER + d;

    float h = 0.f;
    for (int t = 0; t < LL; t++) {
        float u   = xc[(size_t)t * D_INNER];
        float dtv = dtp[(size_t)t * D_INNER];
        float Bn  = bc[(size_t)t * N_DBL + DT_RANK + n];
        float Cn  = bc[(size_t)t * N_DBL + DT_RANK + D_STATE + n];

        h = h * __expf(A * dtv) + (dtv * u) * Bn;

        float p = Cn * h;
        p += __shfl_xor_sync(0xffffffffu, p, 8);
        p += __shfl_xor_sync(0xffffffffu, p, 4);
        p += __shfl_xor_sync(0xffffffffu, p, 2);
        p += __shfl_xor_sync(0xffffffffu, p, 1);

        if (n == 0) {
            float zv = zp[(size_t)t * N_IN];
            float zs = zv / (1.f + __expf(-zv));
            yp[(size_t)t * D_INNER] = (p + u * Dd) * zs;
        }
    }
}

// ---------------------------------------------------------------------------
extern "C" void kernel_launch(void* const* d_in, const int* in_sizes, int n_in,
                              void* d_out, int out_size)
{
    const float* x      = (const float*)d_in[0];
    const float* W_in   = (const float*)d_in[1];
    const float* conv_w = (const float*)d_in[2];
    const float* conv_b = (const float*)d_in[3];
    const float* W_x    = (const float*)d_in[4];
    const float* W_dt   = (const float*)d_in[5];
    const float* b_dt   = (const float*)d_in[6];
    const float* A_log  = (const float*)d_in[7];
    const float* Dvec   = (const float*)d_in[8];
    const float* W_out  = (const float*)d_in[9];
    float* out = (float*)d_out;

    float *xz_p, *xconv_p, *yg_p;
    cudaGetSymbolAddress((void**)&xz_p,    g_xz);
    cudaGetSymbolAddress((void**)&xconv_p, g_xconv);
    cudaGetSymbolAddress((void**)&yg_p,    g_yg);

    // 1) xz = x @ W_in   [4096,768] x [768,3072]
    {
        dim3 grid(N_IN / BN, MROWS / BM);
        sgemm_kernel<<<grid, 256>>>(x, W_in, xz_p, MROWS, N_IN, D_MODEL);
    }
    // 2) causal conv + silu
    {
        int total = MROWS * D_INNER;
        conv_silu_kernel<<<(total + 255) / 256, 256>>>(conv_w, conv_b);
    }
    // 3) x_dbl = x_conv @ W_x
    xdbl_kernel<<<MROWS / 64, 256>>>(W_x);
    // 4) dt = softplus(dt_low @ W_dt + b_dt)
    {
        int total = MROWS * D_INNER;
        dt_kernel<<<(total + 255) / 256, 256>>>(W_dt, b_dt);
    }
    // 5) selective scan + gate
    scan_kernel<<<(BB * D_INNER) / 16, 256>>>(A_log, Dvec);
    // 6) out = y_gated @ W_out   [4096,1536] x [1536,768]
    {
        dim3 grid(D_MODEL / BN, MROWS / BM);
        sgemm_kernel<<<grid, 256>>>(yg_p, W_out, out, MROWS, D_MODEL, D_INNER);
    }
}